// round 1
// baseline (speedup 1.0000x reference)
#include <cuda_runtime.h>
#include <cstdint>

// EdgeUpdate: out = LN(edge_feats + MLP([ns[src], ns[dst], edge_feats]))
// N_NODES=10000, E=640000, D_NODE=64, D_EDGE=128, D_IN=256
#define NWARPS 4
#define EPW    8              // edges per warp
#define TILE   32             // edges per block-iteration (NWARPS*EPW)
#define NTILES 20000          // 640000 / 32

typedef unsigned long long ull;

__device__ __forceinline__ void upk2(ull v, float &a, float &b) {
  asm("mov.b64 {%0, %1}, %2;" : "=f"(a), "=f"(b) : "l"(v));
}
__device__ __forceinline__ ull ffma2(ull a, ull b, ull c) {
  ull d;
  asm("fma.rn.f32x2 %0, %1, %2, %3;" : "=l"(d) : "l"(a), "l"(b), "l"(c));
  return d;
}
__device__ __forceinline__ float silu_f(float x) {
  return x * (1.0f / (1.0f + __expf(-x)));
}

// SMEM layout (floats):
//   sW1i : [128 kpairs][128 outs] float2 (even/odd-k interleaved)  -> 32768 floats
//   sW2i : [ 64 kpairs][128 outs] float2                           -> 16384 floats
//   sb1, sb2, sg, sbt : 128 each                                   ->   512 floats
//   x    : [NWARPS][EPW][256]                                      ->  8192 floats
// total 57856 floats = 231424 bytes (<= 232448 opt-in max)
#define SMEM_FLOATS 57856
#define SMEM_BYTES  (SMEM_FLOATS * 4)

__global__ void __launch_bounds__(128, 1)
edge_update_kernel(const float* __restrict__ nodes,
                   const float* __restrict__ efeat,
                   const int*   __restrict__ srcI,
                   const int*   __restrict__ dstI,
                   const float* __restrict__ W1,
                   const float* __restrict__ b1,
                   const float* __restrict__ W2,
                   const float* __restrict__ b2,
                   const float* __restrict__ gamma,
                   const float* __restrict__ beta,
                   float* __restrict__ out)
{
  extern __shared__ float smem[];
  float* sW1 = smem;                 // 32768
  float* sW2 = smem + 32768;         // 16384
  float* sb1 = smem + 49152;
  float* sb2 = sb1 + 128;
  float* sg  = sb2 + 128;
  float* sbt = sg  + 128;
  float* xall = sbt + 128;           // 4*8*256

  const int tid = threadIdx.x;

  // ---- stage weights, k-pair interleaved ----
  for (int i = tid; i < 16384; i += 128) {
    int kp = i >> 7, o = i & 127;
    ((float2*)sW1)[i] = make_float2(W1[(2 * kp) * 128 + o], W1[(2 * kp + 1) * 128 + o]);
  }
  for (int i = tid; i < 8192; i += 128) {
    int kp = i >> 7, o = i & 127;
    ((float2*)sW2)[i] = make_float2(W2[(2 * kp) * 128 + o], W2[(2 * kp + 1) * 128 + o]);
  }
  if (tid < 128) {
    sb1[tid] = b1[tid]; sb2[tid] = b2[tid];
    sg[tid] = gamma[tid]; sbt[tid] = beta[tid];
  }
  __syncthreads();

  const int warp = tid >> 5, lane = tid & 31;
  float* xw = xall + warp * (EPW * 256);
  const float4 b1v = ((const float4*)sb1)[lane];
  const float4 b2v = ((const float4*)sb2)[lane];
  const float4 gv  = ((const float4*)sg)[lane];
  const float4 btv = ((const float4*)sbt)[lane];

  for (int tile = blockIdx.x; tile < NTILES; tile += gridDim.x) {
    const int e0 = tile * TILE + warp * EPW;
    __syncwarp();   // previous iter's residual reads done before overwriting x

    // ---- gather: x[e] = [src_node(64) | dst_node(64) | edge_feat(128)] ----
#pragma unroll
    for (int e = 0; e < EPW; e++) {
      int n = (lane < 16 ? srcI : dstI)[e0 + e];
      float4 v = ((const float4*)(nodes + (size_t)n * 64))[lane & 15];
      ((float4*)(xw + e * 256))[lane] = v;                       // slots 0..31
      float4 w = ((const float4*)(efeat + (size_t)(e0 + e) * 128))[lane];
      ((float4*)(xw + e * 256))[32 + lane] = w;                  // slots 32..63
    }
    __syncwarp();

    // ---- layer 1: h1 = silu(x @ W1 + b1), K = 256 (128 k-pairs) ----
    ull acc[EPW][4];
#pragma unroll
    for (int e = 0; e < EPW; e++) { acc[e][0] = acc[e][1] = acc[e][2] = acc[e][3] = 0ULL; }
    {
      const ulonglong2* wr = (const ulonglong2*)sW1;
#pragma unroll 2
      for (int kp = 0; kp < 128; kp++) {
        ulonglong2 wab = wr[kp * 64 + 2 * lane];        // pairs for outs 4*lane, 4*lane+1
        ulonglong2 wcd = wr[kp * 64 + 2 * lane + 1];    // pairs for outs 4*lane+2, +3
#pragma unroll
        for (int e = 0; e < EPW; e++) {
          ull xp = *(const ull*)(xw + e * 256 + 2 * kp);   // (x[2kp], x[2kp+1]) broadcast
          acc[e][0] = ffma2(xp, wab.x, acc[e][0]);
          acc[e][1] = ffma2(xp, wab.y, acc[e][1]);
          acc[e][2] = ffma2(xp, wcd.x, acc[e][2]);
          acc[e][3] = ffma2(xp, wcd.y, acc[e][3]);
        }
      }
    }
    __syncwarp();   // everyone done reading x[0..255] before h1 overwrites x[0..127]

#pragma unroll
    for (int e = 0; e < EPW; e++) {
      float lo, hi;
      upk2(acc[e][0], lo, hi); float h0 = silu_f(lo + hi + b1v.x);
      upk2(acc[e][1], lo, hi); float h1_ = silu_f(lo + hi + b1v.y);
      upk2(acc[e][2], lo, hi); float h2 = silu_f(lo + hi + b1v.z);
      upk2(acc[e][3], lo, hi); float h3 = silu_f(lo + hi + b1v.w);
      ((float4*)(xw + e * 256))[lane] = make_float4(h0, h1_, h2, h3);
    }
    __syncwarp();

    // ---- layer 2: h2 = silu(h1 @ W2 + b2), K = 128 (64 k-pairs) ----
#pragma unroll
    for (int e = 0; e < EPW; e++) { acc[e][0] = acc[e][1] = acc[e][2] = acc[e][3] = 0ULL; }
    {
      const ulonglong2* wr = (const ulonglong2*)sW2;
#pragma unroll 2
      for (int kp = 0; kp < 64; kp++) {
        ulonglong2 wab = wr[kp * 64 + 2 * lane];
        ulonglong2 wcd = wr[kp * 64 + 2 * lane + 1];
#pragma unroll
        for (int e = 0; e < EPW; e++) {
          ull xp = *(const ull*)(xw + e * 256 + 2 * kp);
          acc[e][0] = ffma2(xp, wab.x, acc[e][0]);
          acc[e][1] = ffma2(xp, wab.y, acc[e][1]);
          acc[e][2] = ffma2(xp, wcd.x, acc[e][2]);
          acc[e][3] = ffma2(xp, wcd.y, acc[e][3]);
        }
      }
    }

    // ---- epilogue: residual + LayerNorm + affine ----
#pragma unroll
    for (int e = 0; e < EPW; e++) {
      float lo, hi;
      upk2(acc[e][0], lo, hi); float h0 = silu_f(lo + hi + b2v.x);
      upk2(acc[e][1], lo, hi); float h1_ = silu_f(lo + hi + b2v.y);
      upk2(acc[e][2], lo, hi); float h2 = silu_f(lo + hi + b2v.z);
      upk2(acc[e][3], lo, hi); float h3 = silu_f(lo + hi + b2v.w);
      float4 r = ((const float4*)(xw + e * 256 + 128))[lane];   // original edge_feats
      float y0 = r.x + h0, y1 = r.y + h1_, y2 = r.z + h2, y3 = r.w + h3;
      float s = y0 + y1 + y2 + y3;
      float q = y0 * y0 + y1 * y1 + y2 * y2 + y3 * y3;
#pragma unroll
      for (int off = 16; off > 0; off >>= 1) {
        s += __shfl_xor_sync(0xffffffffu, s, off);
        q += __shfl_xor_sync(0xffffffffu, q, off);
      }
      float mean = s * 0.0078125f;                 // /128
      float var  = q * 0.0078125f - mean * mean;
      float rstd = rsqrtf(var + 1e-5f);
      float4 o4;
      o4.x = (y0 - mean) * rstd * gv.x + btv.x;
      o4.y = (y1 - mean) * rstd * gv.y + btv.y;
      o4.z = (y2 - mean) * rstd * gv.z + btv.z;
      o4.w = (y3 - mean) * rstd * gv.w + btv.w;
      ((float4*)(out + (size_t)(e0 + e) * 128))[lane] = o4;
    }
  }
}

extern "C" void kernel_launch(void* const* d_in, const int* in_sizes, int n_in,
                              void* d_out, int out_size) {
  const float* nodes = (const float*)d_in[0];
  const float* efeat = (const float*)d_in[1];
  const int*   srcI  = (const int*)d_in[2];
  const int*   dstI  = (const int*)d_in[3];
  const float* W1    = (const float*)d_in[4];
  const float* b1    = (const float*)d_in[5];
  const float* W2    = (const float*)d_in[6];
  const float* b2    = (const float*)d_in[7];
  const float* gamma = (const float*)d_in[8];
  const float* beta  = (const float*)d_in[9];
  float* out = (float*)d_out;

  cudaFuncSetAttribute(edge_update_kernel,
                       cudaFuncAttributeMaxDynamicSharedMemorySize, SMEM_BYTES);
  int sms = 148;
  cudaDeviceGetAttribute(&sms, cudaDevAttrMultiProcessorCount, 0);
  if (sms < 1) sms = 148;

  edge_update_kernel<<<sms, 128, SMEM_BYTES>>>(
      nodes, efeat, srcI, dstI, W1, b1, W2, b2, gamma, beta, out);
}

// round 3
// speedup vs baseline: 1.2697x; 1.2697x over previous
#include <cuda_runtime.h>
#include <cstdint>

// EdgeUpdate: out = LN(edge_feats + MLP([ns[src], ns[dst], edge_feats]))
// E=640000, D_NODE=64, D_EDGE=128, D_IN=256
// 8 warps/CTA; warp pair {2g,2g+1} shares x-tile of 8 edges (group g),
// each warp computes 64 of the 128 outputs (2 outs/lane).
#define NWARPS 8
#define EPW    8               // edges per group
#define TILE   32              // edges per block iteration (4 groups * 8)
#define NTILES 20000           // 640000 / 32

typedef unsigned long long ull;

__device__ __forceinline__ void upk2(ull v, float &a, float &b) {
  asm("mov.b64 {%0, %1}, %2;" : "=f"(a), "=f"(b) : "l"(v));
}
__device__ __forceinline__ ull ffma2(ull a, ull b, ull c) {
  ull d;
  asm("fma.rn.f32x2 %0, %1, %2, %3;" : "=l"(d) : "l"(a), "l"(b), "l"(c));
  return d;
}
__device__ __forceinline__ float silu_f(float x) {
  return x * (1.0f / (1.0f + __expf(-x)));
}

// SMEM (floats):
//  sW1  [128 kp][128 o] float2 (k-pair interleaved)  32768
//  sW2  [ 64 kp][128 o] float2                       16384
//  sb1,sb2,sg,sbt                                      512
//  x    [4 groups][8 edges][256]                      8192
//  red  [4 groups][2 halves][8 edges] float2           128
#define SMEM_FLOATS (32768 + 16384 + 512 + 8192 + 128)
#define SMEM_BYTES  (SMEM_FLOATS * 4)

__global__ void __launch_bounds__(256, 1)
edge_update_kernel(const float* __restrict__ nodes,
                   const float* __restrict__ efeat,
                   const int*   __restrict__ srcI,
                   const int*   __restrict__ dstI,
                   const float* __restrict__ W1,
                   const float* __restrict__ b1,
                   const float* __restrict__ W2,
                   const float* __restrict__ b2,
                   const float* __restrict__ gamma,
                   const float* __restrict__ beta,
                   float* __restrict__ out)
{
  extern __shared__ float smem[];
  float* sW1 = smem;                 // 32768
  float* sW2 = smem + 32768;         // 16384
  float* sb1 = smem + 49152;
  float* sb2 = sb1 + 128;
  float* sg  = sb2 + 128;
  float* sbt = sg  + 128;
  float* xall = sbt + 128;           // 4*8*256 = 8192
  float* red  = xall + 8192;         // 4*2*8*2 = 128

  const int tid = threadIdx.x;

  // ---- stage weights, k-pair interleaved: sW[kp][o] = (W[2kp][o], W[2kp+1][o]) ----
  for (int i = tid; i < 16384; i += 256) {
    int kp = i >> 7, o = i & 127;
    ((float2*)sW1)[i] = make_float2(W1[(2 * kp) * 128 + o], W1[(2 * kp + 1) * 128 + o]);
  }
  for (int i = tid; i < 8192; i += 256) {
    int kp = i >> 7, o = i & 127;
    ((float2*)sW2)[i] = make_float2(W2[(2 * kp) * 128 + o], W2[(2 * kp + 1) * 128 + o]);
  }
  if (tid < 128) {
    sb1[tid] = b1[tid]; sb2[tid] = b2[tid];
    sg[tid] = gamma[tid]; sbt[tid] = beta[tid];
  }
  __syncthreads();

  const int warp  = tid >> 5, lane = tid & 31;
  const int group = warp >> 1;          // 0..3: which 8-edge tile
  const int sub   = warp & 1;           // 0/1: which 64-out half
  const int widx  = sub * 32 + lane;    // float2/ulonglong2 column index for this lane
  float* xg = xall + group * (EPW * 256);
  float* redg = red + group * 32;       // [2 halves][8 edges] float2

  const float2 b1v = ((const float2*)sb1)[widx];
  const float2 b2v = ((const float2*)sb2)[widx];
  const float2 gv  = ((const float2*)sg)[widx];
  const float2 btv = ((const float2*)sbt)[widx];

  for (int tile = blockIdx.x; tile < NTILES; tile += gridDim.x) {
    const int eg0 = tile * TILE + group * EPW;

    // ---- gather: this warp fills 4 of the group's 8 edges ----
#pragma unroll
    for (int i = 0; i < 4; i++) {
      int e = sub * 4 + i;
      int eg = eg0 + e;
      int n = (lane < 16 ? srcI : dstI)[eg];
      float4 v = ((const float4*)(nodes + (size_t)n * 64))[lane & 15];
      ((float4*)(xg + e * 256))[lane] = v;                  // x[0..127]: src|dst
      float4 w = ((const float4*)(efeat + (size_t)eg * 128))[lane];
      ((float4*)(xg + e * 256))[32 + lane] = w;             // x[128..255]: edge feats
    }
    __syncthreads();   // B1: x ready

    // ---- layer 1: K=256 (64 kp-pairs of 4 k's) ----
    ull acc[EPW][2];
#pragma unroll
    for (int e = 0; e < EPW; e++) { acc[e][0] = acc[e][1] = 0ULL; }
    {
      const ulonglong2* wr = (const ulonglong2*)sW1;
#pragma unroll 2
      for (int kp2 = 0; kp2 < 64; kp2++) {
        ulonglong2 wA = wr[(2 * kp2) * 64 + widx];       // outs (o0,o1), k={4kp2,4kp2+1}
        ulonglong2 wB = wr[(2 * kp2 + 1) * 64 + widx];   // outs (o0,o1), k={4kp2+2,4kp2+3}
#pragma unroll
        for (int e = 0; e < EPW; e++) {
          ulonglong2 xq = ((const ulonglong2*)(xg + e * 256))[kp2];  // x[4kp2..4kp2+3]
          acc[e][0] = ffma2(xq.x, wA.x, acc[e][0]);
          acc[e][1] = ffma2(xq.x, wA.y, acc[e][1]);
          acc[e][0] = ffma2(xq.y, wB.x, acc[e][0]);
          acc[e][1] = ffma2(xq.y, wB.y, acc[e][1]);
        }
      }
    }
    __syncthreads();   // B2: all reads of x[0..255] done

    // ---- silu + store h1 into x[0..127] (each warp writes its 64-out half) ----
#pragma unroll
    for (int e = 0; e < EPW; e++) {
      float lo, hi;
      upk2(acc[e][0], lo, hi); float h0 = silu_f(lo + hi + b1v.x);
      upk2(acc[e][1], lo, hi); float h1 = silu_f(lo + hi + b1v.y);
      ((float2*)(xg + e * 256))[widx] = make_float2(h0, h1);
    }
    __syncthreads();   // B3: h1 ready

    // ---- layer 2: K=128 (32 kp-pairs) ----
#pragma unroll
    for (int e = 0; e < EPW; e++) { acc[e][0] = acc[e][1] = 0ULL; }
    {
      const ulonglong2* wr = (const ulonglong2*)sW2;
#pragma unroll 2
      for (int kp2 = 0; kp2 < 32; kp2++) {
        ulonglong2 wA = wr[(2 * kp2) * 64 + widx];
        ulonglong2 wB = wr[(2 * kp2 + 1) * 64 + widx];
#pragma unroll
        for (int e = 0; e < EPW; e++) {
          ulonglong2 xq = ((const ulonglong2*)(xg + e * 256))[kp2];
          acc[e][0] = ffma2(xq.x, wA.x, acc[e][0]);
          acc[e][1] = ffma2(xq.x, wA.y, acc[e][1]);
          acc[e][0] = ffma2(xq.y, wB.x, acc[e][0]);
          acc[e][1] = ffma2(xq.y, wB.y, acc[e][1]);
        }
      }
    }

    // ---- epilogue: residual, per-half LN partials ----
    float y0[EPW], y1[EPW];
#pragma unroll
    for (int e = 0; e < EPW; e++) {
      float lo, hi;
      upk2(acc[e][0], lo, hi); float h0 = silu_f(lo + hi + b2v.x);
      upk2(acc[e][1], lo, hi); float h1 = silu_f(lo + hi + b2v.y);
      float2 r = ((const float2*)(xg + e * 256 + 128))[widx];  // original edge feats
      y0[e] = r.x + h0;
      y1[e] = r.y + h1;
      float s = y0[e] + y1[e];
      float q = y0[e] * y0[e] + y1[e] * y1[e];
#pragma unroll
      for (int off = 16; off > 0; off >>= 1) {
        s += __shfl_xor_sync(0xffffffffu, s, off);
        q += __shfl_xor_sync(0xffffffffu, q, off);
      }
      if (lane == 0) ((float2*)redg)[sub * 8 + e] = make_float2(s, q);
      if (lane == 1) { /* keep q path live symmetrically (no-op) */ }
      // stash this warp's half-sums in regs via lane-uniform values:
      y0[e] = y0[e]; y1[e] = y1[e];
      acc[e][0] = __double_as_longlong(0.0);  // dead; keeps reg pressure bounded
      // store half sums for own use:
      ((float*)&acc[e][0])[0] = s;  // reuse acc[e][0] low as s (lane-uniform)
      ((float*)&acc[e][0])[1] = q;  // high as q
    }
    __syncthreads();   // B4: partner half-sums visible

#pragma unroll
    for (int e = 0; e < EPW; e++) {
      float2 other = ((const float2*)redg)[(1 - sub) * 8 + e];
      float s_own, q_own;
      upk2(acc[e][0], s_own, q_own);
      float s = s_own + other.x;
      float q = q_own + other.y;
      float mean = s * 0.0078125f;                 // /128
      float var  = q * 0.0078125f - mean * mean;
      float rstd = rsqrtf(var + 1e-5f);
      float2 o2;
      o2.x = (y0[e] - mean) * rstd * gv.x + btv.x;
      o2.y = (y1[e] - mean) * rstd * gv.y + btv.y;
      ((float2*)(out + (size_t)(eg0 + e) * 128))[widx] = o2;
    }
  }
}

extern "C" void kernel_launch(void* const* d_in, const int* in_sizes, int n_in,
                              void* d_out, int out_size) {
  const float* nodes = (const float*)d_in[0];
  const float* efeat = (const float*)d_in[1];
  const int*   srcI  = (const int*)d_in[2];
  const int*   dstI  = (const int*)d_in[3];
  const float* W1    = (const float*)d_in[4];
  const float* b1    = (const float*)d_in[5];
  const float* W2    = (const float*)d_in[6];
  const float* b2    = (const float*)d_in[7];
  const float* gamma = (const float*)d_in[8];
  const float* beta  = (const float*)d_in[9];
  float* out = (float*)d_out;

  cudaFuncSetAttribute(edge_update_kernel,
                       cudaFuncAttributeMaxDynamicSharedMemorySize, SMEM_BYTES);
  int sms = 148;
  cudaDeviceGetAttribute(&sms, cudaDevAttrMultiProcessorCount, 0);
  if (sms < 1) sms = 148;

  edge_update_kernel<<<sms, 256, SMEM_BYTES>>>(
      nodes, efeat, srcI, dstI, W1, b1, W2, b2, gamma, beta, out);
}

// round 6
// speedup vs baseline: 2.4604x; 1.9378x over previous
#include <cuda_runtime.h>
#include <cstdint>

// EdgeUpdate via legacy mma.sync.m16n8k8.tf32 (baseline PTX, works on sm_103 target).
// Tile = 128 edges x 128 outs. 8 warps = 2 M-halves x 4 N-quarters.
// GEMM1: [128,256]x[256,128], K chunked by 64 through smem x-buffer [k][edge].
// GEMM2: [128,128]x[128,128], h1 exchanged through same buffer.
#define THREADS 256
#define NTILES  5000          // 640000 / 128
#define XSTRIDE 136           // 136 mod 32 = 8 -> conflict-free A-frag loads

// smem float offsets
#define OW1 0                 // [256][128] tf32, swizzled n ^ ((k&3)<<3)  : 32768
#define OW2 32768             // [128][128]                                 : 16384
#define OX  49152             // [64][136] chunk buffer / h1 / LN red      :  8704
#define SMEM_FLOATS (49152 + 64*XSTRIDE)
#define SMEM_BYTES  (SMEM_FLOATS * 4)   // 231424 <= 232448

__device__ __forceinline__ unsigned tf32r(float x) {
  unsigned r; asm("cvt.rna.tf32.f32 %0, %1;" : "=r"(r) : "f"(x)); return r;
}
__device__ __forceinline__ float silu_f(float x) {
  return x * (1.0f / (1.0f + __expf(-x)));
}
__device__ __forceinline__ void mma8(float* d, const unsigned* a, const unsigned* b) {
  asm volatile("mma.sync.aligned.m16n8k8.row.col.f32.tf32.tf32.f32 "
    "{%0,%1,%2,%3}, {%4,%5,%6,%7}, {%8,%9}, {%0,%1,%2,%3};"
    : "+f"(d[0]), "+f"(d[1]), "+f"(d[2]), "+f"(d[3])
    : "r"(a[0]), "r"(a[1]), "r"(a[2]), "r"(a[3]), "r"(b[0]), "r"(b[1]));
}

__global__ void __launch_bounds__(THREADS, 1)
edge_update_mma(const float* __restrict__ nodes,
                const float* __restrict__ efeat,
                const int*   __restrict__ srcI,
                const int*   __restrict__ dstI,
                const float* __restrict__ W1,
                const float* __restrict__ b1,
                const float* __restrict__ W2,
                const float* __restrict__ b2,
                const float* __restrict__ gamma,
                const float* __restrict__ beta,
                float* __restrict__ out)
{
  extern __shared__ float smem[];
  unsigned* w1u = (unsigned*)(smem + OW1);
  unsigned* w2u = (unsigned*)(smem + OW2);
  unsigned* sxu = (unsigned*)(smem + OX);

  const int tid  = threadIdx.x;
  const int warp = tid >> 5, lane = tid & 31;
  const int kl = lane & 3, r = lane >> 2;
  const int mi = warp >> 2;            // m-half: edges [64*mi, 64*mi+64)
  const int nj = warp & 3;             // n-quarter: outs [32*nj, 32*nj+32)
  const int mbase = mi * 64;
  const int nbase = nj * 32;

  // ---- stage weights (tf32-rounded, XOR-swizzled) ----
  for (int i = tid; i < 32768; i += THREADS) {
    int k = i >> 7, n = i & 127;
    w1u[k * 128 + (n ^ ((k & 3) << 3))] = tf32r(W1[i]);
  }
  for (int i = tid; i < 16384; i += THREADS) {
    int k = i >> 7, n = i & 127;
    w2u[k * 128 + (n ^ ((k & 3) << 3))] = tf32r(W2[i]);
  }
  // per-lane bias/affine values for this warp's fragment columns
  float b1v[4][2], b2v[4][2], gv[4][2], btv[4][2];
#pragma unroll
  for (int u = 0; u < 4; u++) {
    int n = nbase + u * 8 + 2 * kl;
    b1v[u][0] = b1[n];    b1v[u][1] = b1[n + 1];
    b2v[u][0] = b2[n];    b2v[u][1] = b2[n + 1];
    gv[u][0]  = gamma[n]; gv[u][1]  = gamma[n + 1];
    btv[u][0] = beta[n];  btv[u][1] = beta[n + 1];
  }
  __syncthreads();

  for (int tile = blockIdx.x; tile < NTILES; tile += gridDim.x) {
    const int e0 = tile * 128;

    // ================= GEMM1: D1 = X[128,256] @ W1 =================
    float d1[4][4][4];
#pragma unroll
    for (int t = 0; t < 4; t++)
#pragma unroll
      for (int u = 0; u < 4; u++)
#pragma unroll
        for (int j = 0; j < 4; j++) d1[t][u][j] = 0.f;

#pragma unroll 1
    for (int c = 0; c < 4; c++) {
      __syncthreads();   // previous sX use complete
      // gather chunk c -> sX[k][e], tf32-rounded
      {
        const int e = tid & 127, half = tid >> 7;
        const float* p;
        if (c == 0)      p = nodes + (size_t)srcI[e0 + e] * 64 + half * 32;
        else if (c == 1) p = nodes + (size_t)dstI[e0 + e] * 64 + half * 32;
        else             p = efeat + (size_t)(e0 + e) * 128 + (c - 2) * 64 + half * 32;
        const float4* p4 = (const float4*)p;
#pragma unroll
        for (int j = 0; j < 8; j++) {
          float4 v = p4[j];
          int k = half * 32 + j * 4;
          sxu[(k + 0) * XSTRIDE + e] = tf32r(v.x);
          sxu[(k + 1) * XSTRIDE + e] = tf32r(v.y);
          sxu[(k + 2) * XSTRIDE + e] = tf32r(v.z);
          sxu[(k + 3) * XSTRIDE + e] = tf32r(v.w);
        }
      }
      __syncthreads();

      const int kc = c * 64;
#pragma unroll
      for (int k8 = 0; k8 < 8; k8++) {
        const int kb = k8 * 8;
        unsigned a[4][4];
#pragma unroll
        for (int t = 0; t < 4; t++) {
          int m = mbase + t * 16 + r;
          a[t][0] = sxu[(kb + kl) * XSTRIDE + m];
          a[t][1] = sxu[(kb + kl) * XSTRIDE + m + 8];
          a[t][2] = sxu[(kb + 4 + kl) * XSTRIDE + m];
          a[t][3] = sxu[(kb + 4 + kl) * XSTRIDE + m + 8];
        }
        unsigned b[4][2];
#pragma unroll
        for (int u = 0; u < 4; u++) {
          int n = nbase + u * 8 + r;
          b[u][0] = w1u[(kc + kb + kl) * 128 + (n ^ (kl << 3))];
          b[u][1] = w1u[(kc + kb + 4 + kl) * 128 + (n ^ (kl << 3))];
        }
#pragma unroll
        for (int t = 0; t < 4; t++)
#pragma unroll
          for (int u = 0; u < 4; u++) mma8(d1[t][u], a[t], b[u]);
      }
    }

    // ---- h1 = silu(D1 + b1), tf32-rounded, kept in regs ----
    unsigned h1f[4][4][4];
#pragma unroll
    for (int t = 0; t < 4; t++)
#pragma unroll
      for (int u = 0; u < 4; u++) {
        h1f[t][u][0] = tf32r(silu_f(d1[t][u][0] + b1v[u][0]));
        h1f[t][u][1] = tf32r(silu_f(d1[t][u][1] + b1v[u][1]));
        h1f[t][u][2] = tf32r(silu_f(d1[t][u][2] + b1v[u][0]));
        h1f[t][u][3] = tf32r(silu_f(d1[t][u][3] + b1v[u][1]));
      }

    // ================= GEMM2: D2 = H1[128,128] @ W2 =================
    float d2[4][4][4];
#pragma unroll
    for (int t = 0; t < 4; t++)
#pragma unroll
      for (int u = 0; u < 4; u++)
#pragma unroll
        for (int j = 0; j < 4; j++) d2[t][u][j] = 0.f;

#pragma unroll 1
    for (int c2 = 0; c2 < 2; c2++) {
      __syncthreads();   // sX reads (GEMM1/prev chunk) done
      if ((nj >> 1) == c2) {
        // this warp's h1 n-columns fall in k-range [64*c2, 64*c2+64)
        const int kloc0 = (nj & 1) * 32;
#pragma unroll
        for (int t = 0; t < 4; t++)
#pragma unroll
          for (int u = 0; u < 4; u++) {
            int m = mbase + t * 16 + r;
            int kk = kloc0 + u * 8 + 2 * kl;
            sxu[kk * XSTRIDE + m]           = h1f[t][u][0];
            sxu[(kk + 1) * XSTRIDE + m]     = h1f[t][u][1];
            sxu[kk * XSTRIDE + m + 8]       = h1f[t][u][2];
            sxu[(kk + 1) * XSTRIDE + m + 8] = h1f[t][u][3];
          }
      }
      __syncthreads();

      const int kc = c2 * 64;
#pragma unroll
      for (int k8 = 0; k8 < 8; k8++) {
        const int kb = k8 * 8;
        unsigned a[4][4];
#pragma unroll
        for (int t = 0; t < 4; t++) {
          int m = mbase + t * 16 + r;
          a[t][0] = sxu[(kb + kl) * XSTRIDE + m];
          a[t][1] = sxu[(kb + kl) * XSTRIDE + m + 8];
          a[t][2] = sxu[(kb + 4 + kl) * XSTRIDE + m];
          a[t][3] = sxu[(kb + 4 + kl) * XSTRIDE + m + 8];
        }
        unsigned b[4][2];
#pragma unroll
        for (int u = 0; u < 4; u++) {
          int n = nbase + u * 8 + r;
          b[u][0] = w2u[(kc + kb + kl) * 128 + (n ^ (kl << 3))];
          b[u][1] = w2u[(kc + kb + 4 + kl) * 128 + (n ^ (kl << 3))];
        }
#pragma unroll
        for (int t = 0; t < 4; t++)
#pragma unroll
          for (int u = 0; u < 4; u++) mma8(d2[t][u], a[t], b[u]);
      }
    }

    // ================= epilogue: y = efeat + silu(D2+b2); LN =================
    float y[4][4][4];
    float s0[4], q0[4], s1[4], q1[4];
#pragma unroll
    for (int t = 0; t < 4; t++) { s0[t] = q0[t] = s1[t] = q1[t] = 0.f; }
#pragma unroll
    for (int t = 0; t < 4; t++) {
      int m = mbase + t * 16 + r;
#pragma unroll
      for (int u = 0; u < 4; u++) {
        int n = nbase + u * 8 + 2 * kl;
        float2 ef0 = *(const float2*)(efeat + (size_t)(e0 + m) * 128 + n);
        float2 ef1 = *(const float2*)(efeat + (size_t)(e0 + m + 8) * 128 + n);
        float v0 = ef0.x + silu_f(d2[t][u][0] + b2v[u][0]);
        float v1 = ef0.y + silu_f(d2[t][u][1] + b2v[u][1]);
        float v2 = ef1.x + silu_f(d2[t][u][2] + b2v[u][0]);
        float v3 = ef1.y + silu_f(d2[t][u][3] + b2v[u][1]);
        y[t][u][0] = v0; y[t][u][1] = v1; y[t][u][2] = v2; y[t][u][3] = v3;
        s0[t] += v0 + v1; q0[t] += v0 * v0 + v1 * v1;
        s1[t] += v2 + v3; q1[t] += v2 * v2 + v3 * v3;
      }
    }
    // reduce partials across the 4 lanes sharing a row (lane bits 0..1)
#pragma unroll
    for (int t = 0; t < 4; t++) {
#pragma unroll
      for (int off = 1; off <= 2; off <<= 1) {
        s0[t] += __shfl_xor_sync(0xffffffffu, s0[t], off);
        q0[t] += __shfl_xor_sync(0xffffffffu, q0[t], off);
        s1[t] += __shfl_xor_sync(0xffffffffu, s1[t], off);
        q1[t] += __shfl_xor_sync(0xffffffffu, q1[t], off);
      }
    }
    __syncthreads();    // all GEMM2 sX reads complete
    float2* red = (float2*)sxu;   // [4 nj][128 m]
    if (kl == 0) {
#pragma unroll
      for (int t = 0; t < 4; t++) {
        int m = mbase + t * 16 + r;
        red[nj * 128 + m]     = make_float2(s0[t], q0[t]);
        red[nj * 128 + m + 8] = make_float2(s1[t], q1[t]);
      }
    }
    __syncthreads();
#pragma unroll
    for (int t = 0; t < 4; t++) {
      int m = mbase + t * 16 + r;
      float S0 = 0.f, Q0 = 0.f, S1 = 0.f, Q1 = 0.f;
#pragma unroll
      for (int qd = 0; qd < 4; qd++) {
        float2 v = red[qd * 128 + m];     S0 += v.x; Q0 += v.y;
        float2 w = red[qd * 128 + m + 8]; S1 += w.x; Q1 += w.y;
      }
      float mean0 = S0 * 0.0078125f;
      float var0  = Q0 * 0.0078125f - mean0 * mean0;
      float rs0   = rsqrtf(var0 + 1e-5f);
      float mean1 = S1 * 0.0078125f;
      float var1  = Q1 * 0.0078125f - mean1 * mean1;
      float rs1   = rsqrtf(var1 + 1e-5f);
#pragma unroll
      for (int u = 0; u < 4; u++) {
        int n = nbase + u * 8 + 2 * kl;
        float2 o0, o1;
        o0.x = (y[t][u][0] - mean0) * rs0 * gv[u][0] + btv[u][0];
        o0.y = (y[t][u][1] - mean0) * rs0 * gv[u][1] + btv[u][1];
        o1.x = (y[t][u][2] - mean1) * rs1 * gv[u][0] + btv[u][0];
        o1.y = (y[t][u][3] - mean1) * rs1 * gv[u][1] + btv[u][1];
        *(float2*)(out + (size_t)(e0 + m) * 128 + n)     = o0;
        *(float2*)(out + (size_t)(e0 + m + 8) * 128 + n) = o1;
      }
    }
    // next tile's first __syncthreads orders sX reuse
  }
}

extern "C" void kernel_launch(void* const* d_in, const int* in_sizes, int n_in,
                              void* d_out, int out_size) {
  const float* nodes = (const float*)d_in[0];
  const float* efeat = (const float*)d_in[1];
  const int*   srcI  = (const int*)d_in[2];
  const int*   dstI  = (const int*)d_in[3];
  const float* W1    = (const float*)d_in[4];
  const float* b1    = (const float*)d_in[5];
  const float* W2    = (const float*)d_in[6];
  const float* b2    = (const float*)d_in[7];
  const float* gamma = (const float*)d_in[8];
  const float* beta  = (const float*)d_in[9];
  float* out = (float*)d_out;

  cudaFuncSetAttribute(edge_update_mma,
                       cudaFuncAttributeMaxDynamicSharedMemorySize, SMEM_BYTES);
  int sms = 148;
  cudaDeviceGetAttribute(&sms, cudaDevAttrMultiProcessorCount, 0);
  if (sms < 1) sms = 148;

  edge_update_mma<<<sms, THREADS, SMEM_BYTES>>>(
      nodes, efeat, srcI, dstI, W1, b1, W2, b2, gamma, beta, out);
}

// round 7
// speedup vs baseline: 2.9807x; 1.2114x over previous
#include <cuda_runtime.h>
#include <cstdint>

// EdgeUpdate via mma.sync.m16n8k8.tf32, 512 threads / 16 warps.
// Tile = 128 edges x 128 outs. Warp (mi,nj): mi=warp>>2 (32-edge band), nj=warp&3 (32-out band).
// Operands packed as (k,k+4) float2 pairs -> LDS.64 fragment loads.
#define THREADS 512
#define NTILES  5000          // 640000 / 128
#define PXS     132           // pair-row stride in float2 units (132 mod 16 = 4)
#define HSTRIDE 136           // unpacked h1 stride (floats)

// smem byte offsets
#define OW1 0                 // uint2 [128 pr][128 n]  : 131072 B
#define OW2 131072            // uint2 [ 64 pr][128 n]  :  65536 B
#define OX  196608            // px pairs (33792 B) / h1 unpacked (34816 B) / red
#define SMEM_BYTES (196608 + 64 * HSTRIDE * 4)   // 196608+34816 = 231424

__device__ __forceinline__ unsigned tf32r(float x) {
  unsigned r; asm("cvt.rna.tf32.f32 %0, %1;" : "=r"(r) : "f"(x)); return r;
}
__device__ __forceinline__ float silu_f(float x) {
  return x * (1.0f / (1.0f + __expf(-x)));
}
__device__ __forceinline__ void mma8(float* d, unsigned a0, unsigned a1,
                                     unsigned a2, unsigned a3,
                                     unsigned b0, unsigned b1) {
  asm volatile("mma.sync.aligned.m16n8k8.row.col.f32.tf32.tf32.f32 "
    "{%0,%1,%2,%3}, {%4,%5,%6,%7}, {%8,%9}, {%0,%1,%2,%3};"
    : "+f"(d[0]), "+f"(d[1]), "+f"(d[2]), "+f"(d[3])
    : "r"(a0), "r"(a1), "r"(a2), "r"(a3), "r"(b0), "r"(b1));
}

__global__ void __launch_bounds__(THREADS, 1)
edge_update_mma2(const float* __restrict__ nodes,
                 const float* __restrict__ efeat,
                 const int*   __restrict__ srcI,
                 const int*   __restrict__ dstI,
                 const float* __restrict__ W1,
                 const float* __restrict__ b1,
                 const float* __restrict__ W2,
                 const float* __restrict__ b2,
                 const float* __restrict__ gamma,
                 const float* __restrict__ beta,
                 float* __restrict__ out)
{
  extern __shared__ char smem[];
  uint2* w1p = (uint2*)(smem + OW1);
  uint2* w2p = (uint2*)(smem + OW2);
  uint2* pxu = (uint2*)(smem + OX);          // [32 pr][PXS] pairs
  unsigned* sxu = (unsigned*)(smem + OX);    // [64 k][HSTRIDE] unpacked h1

  const int tid  = threadIdx.x;
  const int warp = tid >> 5, lane = tid & 31;
  const int kl = lane & 3, r = lane >> 2;
  const int mi = warp >> 2;            // 0..3: edges [32*mi, 32*mi+32)
  const int nj = warp & 3;             // 0..3: outs  [32*nj, 32*nj+32)
  const int mbase = mi * 32;
  const int nbase = nj * 32;

  // ---- stage weights as (k, k+4) pairs, tf32-rounded, swizzled n^(kl<<2) ----
  for (int i = tid; i < 16384; i += THREADS) {
    int pr = i >> 7, n = i & 127;
    int k0 = (pr >> 2) * 8 + (pr & 3);
    w1p[pr * 128 + (n ^ ((pr & 3) << 2))] =
        make_uint2(tf32r(W1[k0 * 128 + n]), tf32r(W1[(k0 + 4) * 128 + n]));
  }
  for (int i = tid; i < 8192; i += THREADS) {
    int pr = i >> 7, n = i & 127;
    int k0 = (pr >> 2) * 8 + (pr & 3);
    w2p[pr * 128 + (n ^ ((pr & 3) << 2))] =
        make_uint2(tf32r(W2[k0 * 128 + n]), tf32r(W2[(k0 + 4) * 128 + n]));
  }
  // per-lane bias/affine for this warp's fragment columns
  float b1v[4][2], b2v[4][2], gv[4][2], btv[4][2];
#pragma unroll
  for (int u = 0; u < 4; u++) {
    int n = nbase + u * 8 + 2 * kl;
    b1v[u][0] = b1[n];    b1v[u][1] = b1[n + 1];
    b2v[u][0] = b2[n];    b2v[u][1] = b2[n + 1];
    gv[u][0]  = gamma[n]; gv[u][1]  = gamma[n + 1];
    btv[u][0] = beta[n];  btv[u][1] = beta[n + 1];
  }
  __syncthreads();

  for (int tile = blockIdx.x; tile < NTILES; tile += gridDim.x) {
    const int e0 = tile * 128;

    // ================= GEMM1: D1 = X[128,256] @ W1 =================
    float d1[2][4][4];
#pragma unroll
    for (int t = 0; t < 2; t++)
#pragma unroll
      for (int u = 0; u < 4; u++)
#pragma unroll
        for (int j = 0; j < 4; j++) d1[t][u][j] = 0.f;

#pragma unroll 1
    for (int c = 0; c < 4; c++) {
      __syncthreads();   // previous px use complete
      // gather 64-k chunk c -> px pairs [32 pr][e]
      {
        const int e = tid & 127, q4 = tid >> 7;   // q4: 0..3, two k8-groups each
        const float* base;
        if (c == 0)      base = nodes + (size_t)srcI[e0 + e] * 64;
        else if (c == 1) base = nodes + (size_t)dstI[e0 + e] * 64;
        else             base = efeat + (size_t)(e0 + e) * 128 + (c - 2) * 64;
#pragma unroll
        for (int gg = 0; gg < 2; gg++) {
          int g = q4 * 2 + gg;
          float4 v0 = ((const float4*)(base + g * 8))[0];
          float4 v1 = ((const float4*)(base + g * 8))[1];
          pxu[(4 * g + 0) * PXS + e] = make_uint2(tf32r(v0.x), tf32r(v1.x));
          pxu[(4 * g + 1) * PXS + e] = make_uint2(tf32r(v0.y), tf32r(v1.y));
          pxu[(4 * g + 2) * PXS + e] = make_uint2(tf32r(v0.z), tf32r(v1.z));
          pxu[(4 * g + 3) * PXS + e] = make_uint2(tf32r(v0.w), tf32r(v1.w));
        }
      }
      __syncthreads();

      const int prc = c * 32;   // W pair-row offset of this chunk
#pragma unroll
      for (int k8 = 0; k8 < 8; k8++) {
        const int prb = k8 * 4 + kl;
        uint2 a0[2], a1[2];
#pragma unroll
        for (int t = 0; t < 2; t++) {
          int m = mbase + t * 16 + r;
          a0[t] = pxu[prb * PXS + m];
          a1[t] = pxu[prb * PXS + m + 8];
        }
        uint2 bb[4];
#pragma unroll
        for (int u = 0; u < 4; u++) {
          int n = nbase + u * 8 + r;
          bb[u] = w1p[(prc + prb) * 128 + (n ^ (kl << 2))];
        }
#pragma unroll
        for (int t = 0; t < 2; t++)
#pragma unroll
          for (int u = 0; u < 4; u++)
            mma8(d1[t][u], a0[t].x, a1[t].x, a0[t].y, a1[t].y, bb[u].x, bb[u].y);
      }
    }

    // ---- h1 = silu(D1 + b1), tf32-rounded ----
    unsigned h1f[2][4][4];
#pragma unroll
    for (int t = 0; t < 2; t++)
#pragma unroll
      for (int u = 0; u < 4; u++) {
        h1f[t][u][0] = tf32r(silu_f(d1[t][u][0] + b1v[u][0]));
        h1f[t][u][1] = tf32r(silu_f(d1[t][u][1] + b1v[u][1]));
        h1f[t][u][2] = tf32r(silu_f(d1[t][u][2] + b1v[u][0]));
        h1f[t][u][3] = tf32r(silu_f(d1[t][u][3] + b1v[u][1]));
      }

    // ================= GEMM2: D2 = H1[128,128] @ W2 =================
    float d2[2][4][4];
#pragma unroll
    for (int t = 0; t < 2; t++)
#pragma unroll
      for (int u = 0; u < 4; u++)
#pragma unroll
        for (int j = 0; j < 4; j++) d2[t][u][j] = 0.f;

#pragma unroll 1
    for (int c2 = 0; c2 < 2; c2++) {
      __syncthreads();   // px/sxu reads done
      if ((nj >> 1) == c2) {
        const int kloc0 = (nj & 1) * 32;
#pragma unroll
        for (int t = 0; t < 2; t++)
#pragma unroll
          for (int u = 0; u < 4; u++) {
            int m = mbase + t * 16 + r;
            int kk = kloc0 + u * 8 + 2 * kl;
            sxu[kk * HSTRIDE + m]           = h1f[t][u][0];
            sxu[(kk + 1) * HSTRIDE + m]     = h1f[t][u][1];
            sxu[kk * HSTRIDE + m + 8]       = h1f[t][u][2];
            sxu[(kk + 1) * HSTRIDE + m + 8] = h1f[t][u][3];
          }
      }
      __syncthreads();

      const int prc = c2 * 32;
#pragma unroll
      for (int k8 = 0; k8 < 8; k8++) {
        const int kb = k8 * 8;
        unsigned a[2][4];
#pragma unroll
        for (int t = 0; t < 2; t++) {
          int m = mbase + t * 16 + r;
          a[t][0] = sxu[(kb + kl) * HSTRIDE + m];
          a[t][1] = sxu[(kb + kl) * HSTRIDE + m + 8];
          a[t][2] = sxu[(kb + 4 + kl) * HSTRIDE + m];
          a[t][3] = sxu[(kb + 4 + kl) * HSTRIDE + m + 8];
        }
        uint2 bb[4];
#pragma unroll
        for (int u = 0; u < 4; u++) {
          int n = nbase + u * 8 + r;
          bb[u] = w2p[(prc + k8 * 4 + kl) * 128 + (n ^ (kl << 2))];
        }
#pragma unroll
        for (int t = 0; t < 2; t++)
#pragma unroll
          for (int u = 0; u < 4; u++)
            mma8(d2[t][u], a[t][0], a[t][1], a[t][2], a[t][3], bb[u].x, bb[u].y);
      }
    }

    // ================= epilogue: y = efeat + silu(D2+b2); LN =================
    float y[2][4][4];
    float s0[2], q0[2], s1[2], q1[2];
#pragma unroll
    for (int t = 0; t < 2; t++) { s0[t] = q0[t] = s1[t] = q1[t] = 0.f; }
#pragma unroll
    for (int t = 0; t < 2; t++) {
      int m = mbase + t * 16 + r;
#pragma unroll
      for (int u = 0; u < 4; u++) {
        int n = nbase + u * 8 + 2 * kl;
        float2 ef0 = *(const float2*)(efeat + (size_t)(e0 + m) * 128 + n);
        float2 ef1 = *(const float2*)(efeat + (size_t)(e0 + m + 8) * 128 + n);
        float v0 = ef0.x + silu_f(d2[t][u][0] + b2v[u][0]);
        float v1 = ef0.y + silu_f(d2[t][u][1] + b2v[u][1]);
        float v2 = ef1.x + silu_f(d2[t][u][2] + b2v[u][0]);
        float v3 = ef1.y + silu_f(d2[t][u][3] + b2v[u][1]);
        y[t][u][0] = v0; y[t][u][1] = v1; y[t][u][2] = v2; y[t][u][3] = v3;
        s0[t] += v0 + v1; q0[t] += v0 * v0 + v1 * v1;
        s1[t] += v2 + v3; q1[t] += v2 * v2 + v3 * v3;
      }
    }
#pragma unroll
    for (int t = 0; t < 2; t++) {
#pragma unroll
      for (int off = 1; off <= 2; off <<= 1) {
        s0[t] += __shfl_xor_sync(0xffffffffu, s0[t], off);
        q0[t] += __shfl_xor_sync(0xffffffffu, q0[t], off);
        s1[t] += __shfl_xor_sync(0xffffffffu, s1[t], off);
        q1[t] += __shfl_xor_sync(0xffffffffu, q1[t], off);
      }
    }
    __syncthreads();   // GEMM2 sxu reads complete
    float2* red = (float2*)sxu;   // [4 nj][128 m]
    if (kl == 0) {
#pragma unroll
      for (int t = 0; t < 2; t++) {
        int m = mbase + t * 16 + r;
        red[nj * 128 + m]     = make_float2(s0[t], q0[t]);
        red[nj * 128 + m + 8] = make_float2(s1[t], q1[t]);
      }
    }
    __syncthreads();
#pragma unroll
    for (int t = 0; t < 2; t++) {
      int m = mbase + t * 16 + r;
      float S0 = 0.f, Q0 = 0.f, S1 = 0.f, Q1 = 0.f;
#pragma unroll
      for (int qd = 0; qd < 4; qd++) {
        float2 v = red[qd * 128 + m];     S0 += v.x; Q0 += v.y;
        float2 w = red[qd * 128 + m + 8]; S1 += w.x; Q1 += w.y;
      }
      float mean0 = S0 * 0.0078125f;
      float var0  = Q0 * 0.0078125f - mean0 * mean0;
      float rs0   = rsqrtf(var0 + 1e-5f);
      float mean1 = S1 * 0.0078125f;
      float var1  = Q1 * 0.0078125f - mean1 * mean1;
      float rs1   = rsqrtf(var1 + 1e-5f);
#pragma unroll
      for (int u = 0; u < 4; u++) {
        int n = nbase + u * 8 + 2 * kl;
        float2 o0, o1;
        o0.x = (y[t][u][0] - mean0) * rs0 * gv[u][0] + btv[u][0];
        o0.y = (y[t][u][1] - mean0) * rs0 * gv[u][1] + btv[u][1];
        o1.x = (y[t][u][2] - mean1) * rs1 * gv[u][0] + btv[u][0];
        o1.y = (y[t][u][3] - mean1) * rs1 * gv[u][1] + btv[u][1];
        *(float2*)(out + (size_t)(e0 + m) * 128 + n)     = o0;
        *(float2*)(out + (size_t)(e0 + m + 8) * 128 + n) = o1;
      }
    }
    // next tile's first __syncthreads orders sxu/red reuse
  }
}

extern "C" void kernel_launch(void* const* d_in, const int* in_sizes, int n_in,
                              void* d_out, int out_size) {
  const float* nodes = (const float*)d_in[0];
  const float* efeat = (const float*)d_in[1];
  const int*   srcI  = (const int*)d_in[2];
  const int*   dstI  = (const int*)d_in[3];
  const float* W1    = (const float*)d_in[4];
  const float* b1    = (const float*)d_in[5];
  const float* W2    = (const float*)d_in[6];
  const float* b2    = (const float*)d_in[7];
  const float* gamma = (const float*)d_in[8];
  const float* beta  = (const float*)d_in[9];
  float* out = (float*)d_out;

  cudaFuncSetAttribute(edge_update_mma2,
                       cudaFuncAttributeMaxDynamicSharedMemorySize, SMEM_BYTES);
  int sms = 148;
  cudaDeviceGetAttribute(&sms, cudaDevAttrMultiProcessorCount, 0);
  if (sms < 1) sms = 148;

  edge_update_mma2<<<sms, THREADS, SMEM_BYTES>>>(
      nodes, efeat, srcI, dstI, W1, b1, W2, b2, gamma, beta, out);
}